// round 2
// baseline (speedup 1.0000x reference)
#include <cuda_runtime.h>
#include <cuda_fp16.h>
#include <mma.h>

namespace wm = nvcuda::wmma;

#define BATCH 32
#define HIMG 28
#define CDIM 384
#define TQ 785
#define TKV 197
#define NHEAD 6
#define HD 64
#define ATT_SCALE 0.051031036307982884f  /* 1/sqrt(384) -- DIM, not head_dim */

// ---------------- scratch (static device globals; no allocation) ----------------
__device__ float g_qin[BATCH * TQ * CDIM];
__device__ float g_kin[BATCH * TKV * CDIM];
__device__ float g_vin[BATCH * TKV * CDIM];
__device__ float g_q[BATCH * TQ * CDIM];    // [b][h][t][d]
__device__ float g_k[BATCH * TKV * CDIM];   // [b][h][t][d]
__device__ float g_v[BATCH * TKV * CDIM];   // [b][h][t][d]
__device__ float g_att[BATCH * TQ * CDIM];  // [b][t][h*64+d]

// Split an fp32 into hi/lo fp16 so hi+lo reproduces ~22 mantissa bits.
__device__ __forceinline__ void split2(float v, __half& hi, __half& lo) {
    __half h = __float2half_rn(v);
    hi = h;
    lo = __float2half_rn(v - __half2float(h));
}

// ---------------- depthwise conv3x3 + BN (+ cls-token passthrough) ----------------
__global__ void conv_bn_kernel(const float* __restrict__ x,
                               const float* __restrict__ cw,     // [C][3][3]
                               const float* __restrict__ gamma,
                               const float* __restrict__ beta,
                               const float* __restrict__ mean,
                               const float* __restrict__ var,
                               float* __restrict__ out,          // [B][Tout][C]
                               int Hout, int stride)
{
    int idx = blockIdx.x * blockDim.x + threadIdx.x;
    int Tout = Hout * Hout + 1;
    int c = idx % CDIM;
    int t = (idx / CDIM) % Tout;
    int b = idx / (CDIM * Tout);
    if (b >= BATCH) return;

    if (t == 0) {  // cls token passthrough
        out[idx] = x[(size_t)(b * TQ) * CDIM + c];
        return;
    }
    int p = t - 1;
    int oi = p / Hout, oj = p % Hout;
    float inv  = gamma[c] * rsqrtf(var[c] + 1e-5f);
    float bias = beta[c] - mean[c] * inv;
    float acc = 0.f;
#pragma unroll
    for (int ky = 0; ky < 3; ky++) {
        int iy = oi * stride + ky - 1;
        if (iy < 0 || iy >= HIMG) continue;
#pragma unroll
        for (int kx = 0; kx < 3; kx++) {
            int ix = oj * stride + kx - 1;
            if (ix < 0 || ix >= HIMG) continue;
            acc += cw[c * 9 + ky * 3 + kx] *
                   x[(size_t)(b * TQ + 1 + iy * HIMG + ix) * CDIM + c];
        }
    }
    out[idx] = acc * inv + bias;
}

// ---------------- split-fp16 GEMM:  Y[m][n] = sum_k X[m][k] * W[n][k] (+bias) ----------------
// CTA tile 64x64, K-step 32, 256 threads (8 warps: 2 x 4 over (m,n)).
template <bool HEADSPLIT, bool BIAS>
__global__ void gemm_split_kernel(const float* __restrict__ X,
                                  const float* __restrict__ W,
                                  const float* __restrict__ bias,
                                  float* __restrict__ Y,
                                  int M, int Ttok)
{
    __shared__ __half Ah[64][40], Al[64][40], Bh[64][40], Bl[64][40];
    __shared__ float Cs[64][68];
    const int m0 = blockIdx.x * 64, n0 = blockIdx.y * 64;
    const int tid = threadIdx.x;
    const int wid = tid >> 5;
    const int wmi = wid >> 2, wni = wid & 3;

    wm::fragment<wm::accumulator, 16, 16, 16, float> acc[2];
    wm::fill_fragment(acc[0], 0.f);
    wm::fill_fragment(acc[1], 0.f);

    for (int k0 = 0; k0 < CDIM; k0 += 32) {
        __syncthreads();
#pragma unroll
        for (int i = 0; i < 8; i++) {
            int e = i * 256 + tid;
            int r = e >> 5, cc = e & 31;
            int m = m0 + r;
            float av = (m < M) ? X[(size_t)m * CDIM + k0 + cc] : 0.f;
            split2(av, Ah[r][cc], Al[r][cc]);
            float bv = W[(size_t)(n0 + r) * CDIM + k0 + cc];
            split2(bv, Bh[r][cc], Bl[r][cc]);
        }
        __syncthreads();
#pragma unroll
        for (int ks = 0; ks < 2; ks++) {
            wm::fragment<wm::matrix_a, 16, 16, 16, __half, wm::row_major> ah0, ah1, al0, al1;
            wm::fragment<wm::matrix_b, 16, 16, 16, __half, wm::col_major> bh, bl;
            wm::load_matrix_sync(ah0, &Ah[wmi * 32][ks * 16], 40);
            wm::load_matrix_sync(ah1, &Ah[wmi * 32 + 16][ks * 16], 40);
            wm::load_matrix_sync(al0, &Al[wmi * 32][ks * 16], 40);
            wm::load_matrix_sync(al1, &Al[wmi * 32 + 16][ks * 16], 40);
            wm::load_matrix_sync(bh, &Bh[wni * 16][ks * 16], 40);
            wm::load_matrix_sync(bl, &Bl[wni * 16][ks * 16], 40);
            wm::mma_sync(acc[0], ah0, bh, acc[0]);
            wm::mma_sync(acc[1], ah1, bh, acc[1]);
            wm::mma_sync(acc[0], ah0, bl, acc[0]);
            wm::mma_sync(acc[1], ah1, bl, acc[1]);
            wm::mma_sync(acc[0], al0, bh, acc[0]);
            wm::mma_sync(acc[1], al1, bh, acc[1]);
        }
    }
    __syncthreads();
    wm::store_matrix_sync(&Cs[wmi * 32][wni * 16], acc[0], 68, wm::mem_row_major);
    wm::store_matrix_sync(&Cs[wmi * 32 + 16][wni * 16], acc[1], 68, wm::mem_row_major);
    __syncthreads();
#pragma unroll
    for (int i = 0; i < 16; i++) {
        int e = i * 256 + tid;
        int r = e >> 6, cc = e & 63;
        int m = m0 + r, n = n0 + cc;
        if (m < M) {
            float val = Cs[r][cc];
            if (BIAS) val += bias[n];
            if (HEADSPLIT) {
                int b = m / Ttok, t = m % Ttok;
                Y[(((size_t)(b * NHEAD + (n >> 6)) * Ttok + t) << 6) + (n & 63)] = val;
            } else {
                Y[(size_t)m * CDIM + n] = val;
            }
        }
    }
}

// ---------------- attention: per (b,h) x 64-query block ----------------
// S = (Q K^T) * scale -> softmax -> O = P V, split-fp16 MMAs, fp32 softmax.
__global__ void attn_kernel(const float* __restrict__ Q,
                            const float* __restrict__ K,
                            const float* __restrict__ V,
                            float* __restrict__ O)
{
    extern __shared__ char smraw[];
    __half (*Qh)[72] = reinterpret_cast<__half(*)[72]>(smraw);
    __half (*Ql)[72] = reinterpret_cast<__half(*)[72]>(smraw + 9216);
    __half (*Ph)[72] = reinterpret_cast<__half(*)[72]>(smraw + 18432);  // K hi, then P hi
    __half (*Pl)[72] = reinterpret_cast<__half(*)[72]>(smraw + 27648);  // K lo, then P lo
    __half (*Vh)[72] = reinterpret_cast<__half(*)[72]>(smraw + 36864);
    __half (*Vl)[72] = reinterpret_cast<__half(*)[72]>(smraw + 46080);
    float (*S)[264]  = reinterpret_cast<float(*)[264]>(smraw + 55296);  // 64 x 264

    const int bh = blockIdx.y;
    const int q0 = blockIdx.x * 64;
    const float* Qp = Q + (size_t)bh * TQ * HD;
    const float* Kp = K + (size_t)bh * TKV * HD;
    const float* Vp = V + (size_t)bh * TKV * HD;
    const int tid = threadIdx.x;
    const int wid = tid >> 5, lane = tid & 31;
    const int wmi = wid >> 2, wni = wid & 3;

    // load Q block (zero-pad rows >= TQ)
#pragma unroll
    for (int i = 0; i < 16; i++) {
        int e = i * 256 + tid, r = e >> 6, cc = e & 63;
        int t = q0 + r;
        float v = (t < TQ) ? Qp[(size_t)t * HD + cc] : 0.f;
        split2(v, Qh[r][cc], Ql[r][cc]);
    }

    // ---- S = Q K^T over 4 chunks of 64 kv rows ----
    for (int kc = 0; kc < 4; kc++) {
        __syncthreads();
#pragma unroll
        for (int i = 0; i < 16; i++) {
            int e = i * 256 + tid, r = e >> 6, cc = e & 63;
            int t = kc * 64 + r;
            float v = (t < TKV) ? Kp[(size_t)t * HD + cc] : 0.f;
            split2(v, Ph[r][cc], Pl[r][cc]);
        }
        __syncthreads();
        wm::fragment<wm::accumulator, 16, 16, 16, float> sa[2];
        wm::fill_fragment(sa[0], 0.f);
        wm::fill_fragment(sa[1], 0.f);
#pragma unroll
        for (int ks = 0; ks < 4; ks++) {
            wm::fragment<wm::matrix_a, 16, 16, 16, __half, wm::row_major> qh0, qh1, ql0, ql1;
            wm::fragment<wm::matrix_b, 16, 16, 16, __half, wm::col_major> kh, kl;
            wm::load_matrix_sync(qh0, &Qh[wmi * 32][ks * 16], 72);
            wm::load_matrix_sync(qh1, &Qh[wmi * 32 + 16][ks * 16], 72);
            wm::load_matrix_sync(ql0, &Ql[wmi * 32][ks * 16], 72);
            wm::load_matrix_sync(ql1, &Ql[wmi * 32 + 16][ks * 16], 72);
            wm::load_matrix_sync(kh, &Ph[wni * 16][ks * 16], 72);
            wm::load_matrix_sync(kl, &Pl[wni * 16][ks * 16], 72);
            wm::mma_sync(sa[0], qh0, kh, sa[0]);
            wm::mma_sync(sa[1], qh1, kh, sa[1]);
            wm::mma_sync(sa[0], qh0, kl, sa[0]);
            wm::mma_sync(sa[1], qh1, kl, sa[1]);
            wm::mma_sync(sa[0], ql0, kh, sa[0]);
            wm::mma_sync(sa[1], ql1, kh, sa[1]);
        }
        wm::store_matrix_sync(&S[wmi * 32][kc * 64 + wni * 16], sa[0], 264, wm::mem_row_major);
        wm::store_matrix_sync(&S[wmi * 32 + 16][kc * 64 + wni * 16], sa[1], 264, wm::mem_row_major);
    }
    __syncthreads();

    // ---- softmax (fp32), rows per warp; pad cols [TKV,264) zeroed ----
#pragma unroll
    for (int rr = 0; rr < 8; rr++) {
        int r = wid * 8 + rr;
        float mx = -1e30f;
        for (int j = lane; j < TKV; j += 32) mx = fmaxf(mx, S[r][j]);
#pragma unroll
        for (int o = 16; o; o >>= 1) mx = fmaxf(mx, __shfl_xor_sync(0xffffffffu, mx, o));
        float sum = 0.f;
        for (int j = lane; j < 264; j += 32) {
            float p = (j < TKV) ? __expf((S[r][j] - mx) * ATT_SCALE) : 0.f;
            S[r][j] = p;
            sum += p;
        }
#pragma unroll
        for (int o = 16; o; o >>= 1) sum += __shfl_xor_sync(0xffffffffu, sum, o);
        float inv = 1.f / sum;
        for (int j = lane; j < TKV; j += 32) S[r][j] *= inv;
    }
    __syncthreads();

    // ---- O = P V over 4 chunks ----
    wm::fragment<wm::accumulator, 16, 16, 16, float> oa[2];
    wm::fill_fragment(oa[0], 0.f);
    wm::fill_fragment(oa[1], 0.f);
    for (int kc = 0; kc < 4; kc++) {
        __syncthreads();
#pragma unroll
        for (int i = 0; i < 16; i++) {
            int e = i * 256 + tid, r = e >> 6, cc = e & 63;
            split2(S[r][kc * 64 + cc], Ph[r][cc], Pl[r][cc]);
            int t = kc * 64 + r;
            float v = (t < TKV) ? Vp[(size_t)t * HD + cc] : 0.f;
            split2(v, Vh[r][cc], Vl[r][cc]);
        }
        __syncthreads();
#pragma unroll
        for (int ks = 0; ks < 4; ks++) {
            wm::fragment<wm::matrix_a, 16, 16, 16, __half, wm::row_major> ph0, ph1, pl0, pl1;
            wm::fragment<wm::matrix_b, 16, 16, 16, __half, wm::row_major> vbh, vbl;
            wm::load_matrix_sync(ph0, &Ph[wmi * 32][ks * 16], 72);
            wm::load_matrix_sync(ph1, &Ph[wmi * 32 + 16][ks * 16], 72);
            wm::load_matrix_sync(pl0, &Pl[wmi * 32][ks * 16], 72);
            wm::load_matrix_sync(pl1, &Pl[wmi * 32 + 16][ks * 16], 72);
            wm::load_matrix_sync(vbh, &Vh[ks * 16][wni * 16], 72);
            wm::load_matrix_sync(vbl, &Vl[ks * 16][wni * 16], 72);
            wm::mma_sync(oa[0], ph0, vbh, oa[0]);
            wm::mma_sync(oa[1], ph1, vbh, oa[1]);
            wm::mma_sync(oa[0], ph0, vbl, oa[0]);
            wm::mma_sync(oa[1], ph1, vbl, oa[1]);
            wm::mma_sync(oa[0], pl0, vbh, oa[0]);
            wm::mma_sync(oa[1], pl1, vbh, oa[1]);
        }
    }
    __syncthreads();
    wm::store_matrix_sync(&S[wmi * 32][wni * 16], oa[0], 264, wm::mem_row_major);
    wm::store_matrix_sync(&S[wmi * 32 + 16][wni * 16], oa[1], 264, wm::mem_row_major);
    __syncthreads();

    const int b = bh / NHEAD, hh = bh % NHEAD;
#pragma unroll
    for (int i = 0; i < 16; i++) {
        int e = i * 256 + tid, r = e >> 6, cc = e & 63;
        int t = q0 + r;
        if (t < TQ) O[((size_t)(b * TQ + t)) * CDIM + hh * HD + cc] = S[r][cc];
    }
}

// ---------------- launch ----------------
extern "C" void kernel_launch(void* const* d_in, const int* in_sizes, int n_in,
                              void* d_out, int out_size)
{
    const float* x      = (const float*)d_in[0];
    const float* conv_w = (const float*)d_in[1];  // [3][C][1][3][3]
    const float* gamma  = (const float*)d_in[2];  // [3][C]
    const float* beta   = (const float*)d_in[3];
    const float* mean   = (const float*)d_in[4];
    const float* var    = (const float*)d_in[5];
    const float* w_q    = (const float*)d_in[6];
    const float* w_k    = (const float*)d_in[7];
    const float* w_v    = (const float*)d_in[8];
    const float* w_proj = (const float*)d_in[9];
    const float* b_proj = (const float*)d_in[10];
    float* out = (float*)d_out;

    void *pqi, *pki, *pvi, *pq, *pk, *pv, *pa;
    cudaGetSymbolAddress(&pqi, g_qin);
    cudaGetSymbolAddress(&pki, g_kin);
    cudaGetSymbolAddress(&pvi, g_vin);
    cudaGetSymbolAddress(&pq, g_q);
    cudaGetSymbolAddress(&pk, g_k);
    cudaGetSymbolAddress(&pv, g_v);
    cudaGetSymbolAddress(&pa, g_att);

    // 1-3: depthwise conv + BN
    conv_bn_kernel<<<(BATCH * TQ * CDIM) / 256, 256>>>(
        x, conv_w, gamma, beta, mean, var, (float*)pqi, 28, 1);
    conv_bn_kernel<<<(BATCH * TKV * CDIM) / 256, 256>>>(
        x, conv_w + CDIM * 9, gamma + CDIM, beta + CDIM, mean + CDIM, var + CDIM,
        (float*)pki, 14, 2);
    conv_bn_kernel<<<(BATCH * TKV * CDIM) / 256, 256>>>(
        x, conv_w + 2 * CDIM * 9, gamma + 2 * CDIM, beta + 2 * CDIM, mean + 2 * CDIM,
        var + 2 * CDIM, (float*)pvi, 14, 2);

    // 4-6: QKV projections (head-split output layout)
    const int MQ = BATCH * TQ;    // 25120
    const int MKV = BATCH * TKV;  // 6304
    dim3 gq((MQ + 63) / 64, 6), gkv((MKV + 63) / 64, 6);
    gemm_split_kernel<true, false><<<gq, 256>>>((const float*)pqi, w_q, nullptr, (float*)pq, MQ, TQ);
    gemm_split_kernel<true, false><<<gkv, 256>>>((const float*)pki, w_k, nullptr, (float*)pk, MKV, TKV);
    gemm_split_kernel<true, false><<<gkv, 256>>>((const float*)pvi, w_v, nullptr, (float*)pv, MKV, TKV);

    // 7: attention
    const int ATT_SMEM = 55296 + 64 * 264 * 4;  // 122880
    cudaFuncSetAttribute(attn_kernel, cudaFuncAttributeMaxDynamicSharedMemorySize, ATT_SMEM);
    attn_kernel<<<dim3((TQ + 63) / 64, BATCH * NHEAD), 256, ATT_SMEM>>>(
        (const float*)pq, (const float*)pk, (const float*)pv, (float*)pa);

    // 8: output projection + bias
    gemm_split_kernel<false, true><<<gq, 256>>>((const float*)pa, w_proj, b_proj, out, MQ, TQ);
}

// round 5
// speedup vs baseline: 1.5674x; 1.5674x over previous
#include <cuda_runtime.h>
#include <cuda_fp16.h>
#include <mma.h>
#include <cstdint>

namespace wm = nvcuda::wmma;

#define BATCH 32
#define HIMG 28
#define CDIM 384
#define TQ 785
#define TKV 197
#define NHEAD 6
#define HD 64
#define ATT_SCALE 0.051031036307982884f  /* 1/sqrt(384) -- DIM, not head_dim */

// ---------------- persistent split-half planes (no allocation) ----------------
__device__ __half g_xqh[BATCH*TQ*CDIM],  g_xql[BATCH*TQ*CDIM];
__device__ __half g_xkh[BATCH*TKV*CDIM], g_xkl[BATCH*TKV*CDIM];
__device__ __half g_xvh[BATCH*TKV*CDIM], g_xvl[BATCH*TKV*CDIM];
__device__ __half g_qh[BATCH*TQ*CDIM],   g_ql[BATCH*TQ*CDIM];    // [b][h][t][64]
__device__ __half g_kh[BATCH*TKV*CDIM],  g_kl[BATCH*TKV*CDIM];   // [b][h][t][64]
__device__ __half g_vh[BATCH*TKV*CDIM],  g_vl[BATCH*TKV*CDIM];   // [b][h][t][64]
__device__ __half g_ath[BATCH*TQ*CDIM],  g_atl[BATCH*TQ*CDIM];   // [b][t][384]
__device__ __half g_wh[4*CDIM*CDIM],     g_wl[4*CDIM*CDIM];

__device__ __forceinline__ void split2(float v, __half& hi, __half& lo) {
    __half h = __float2half_rn(v);
    hi = h;
    lo = __float2half_rn(v - __half2float(h));
}

// cp.async helpers (LDGSTS). src-size=0 zero-fills without touching memory.
__device__ __forceinline__ void cp_async16(void* sdst, const void* gsrc, bool pred) {
    unsigned int s = (unsigned int)__cvta_generic_to_shared(sdst);
    int bytes = pred ? 16 : 0;
    asm volatile("cp.async.cg.shared.global [%0], [%1], 16, %2;\n"
                 :: "r"(s), "l"(gsrc), "r"(bytes));
}
#define CP_COMMIT() asm volatile("cp.async.commit_group;\n" ::: "memory")
#define CP_WAIT0()  asm volatile("cp.async.wait_group 0;\n" ::: "memory")
#define CP_WAIT1()  asm volatile("cp.async.wait_group 1;\n" ::: "memory")

// ---------------- weight split ----------------
__global__ void split_w_kernel(const float* __restrict__ src, __half* __restrict__ h,
                               __half* __restrict__ l, int n)
{
    int i = blockIdx.x * blockDim.x + threadIdx.x;
    if (i < n) split2(src[i], h[i], l[i]);
}

// ---------------- depthwise conv3x3 + BN -> split halves ----------------
__global__ void conv_bn_kernel(const float* __restrict__ x,
                               const float* __restrict__ cw,
                               const float* __restrict__ gamma,
                               const float* __restrict__ beta,
                               const float* __restrict__ mean,
                               const float* __restrict__ var,
                               __half* __restrict__ outh, __half* __restrict__ outl,
                               int Hout, int stride)
{
    int idx = blockIdx.x * blockDim.x + threadIdx.x;
    int Tout = Hout * Hout + 1;
    int c = idx % CDIM;
    int t = (idx / CDIM) % Tout;
    int b = idx / (CDIM * Tout);
    if (b >= BATCH) return;

    float val;
    if (t == 0) {
        val = x[(size_t)(b * TQ) * CDIM + c];
    } else {
        int p = t - 1;
        int oi = p / Hout, oj = p % Hout;
        float inv  = gamma[c] * rsqrtf(var[c] + 1e-5f);
        float bias = beta[c] - mean[c] * inv;
        float acc = 0.f;
#pragma unroll
        for (int ky = 0; ky < 3; ky++) {
            int iy = oi * stride + ky - 1;
            if (iy < 0 || iy >= HIMG) continue;
#pragma unroll
            for (int kx = 0; kx < 3; kx++) {
                int ix = oj * stride + kx - 1;
                if (ix < 0 || ix >= HIMG) continue;
                acc += cw[c * 9 + ky * 3 + kx] *
                       x[(size_t)(b * TQ + 1 + iy * HIMG + ix) * CDIM + c];
            }
        }
        val = acc * inv + bias;
    }
    split2(val, outh[idx], outl[idx]);
}

// ---------------- split-half GEMM: Y[m][n] = sum_k X[m][k]*W[n][k] ----------------
// CTA 128x64, K-step 32, cp.async double-buffered, 256 threads, warp tile 32x32.
template <bool HEADSPLIT, bool BIAS>
__global__ __launch_bounds__(256, 2)
void gemm_half_kernel(const __half* __restrict__ Xh, const __half* __restrict__ Xl,
                      const __half* __restrict__ Wh, const __half* __restrict__ Wl,
                      const float* __restrict__ bias,
                      float* __restrict__ Yf, __half* __restrict__ Yh, __half* __restrict__ Yl,
                      int M, int Ttok)
{
    __shared__ __half sA[2][2][128][40];
    __shared__ __half sB[2][2][64][40];

    const int m0 = blockIdx.x * 128, n0 = blockIdx.y * 64;
    const int tid = threadIdx.x, wid = tid >> 5;
    const int wmi = wid >> 1, wni = wid & 1;

    wm::fragment<wm::accumulator, 16, 16, 16, float> acc[2][2];
#pragma unroll
    for (int i = 0; i < 2; i++)
#pragma unroll
        for (int j = 0; j < 2; j++) wm::fill_fragment(acc[i][j], 0.f);

    auto load_stage = [&](int st, int k0) {
#pragma unroll
        for (int p = 0; p < 2; p++) {
            const __half* src = p ? Xl : Xh;
#pragma unroll
            for (int i = 0; i < 2; i++) {
                int c = i * 256 + tid;
                int r = c >> 2, kc = (c & 3) * 8;
                bool v = (m0 + r) < M;
                cp_async16(&sA[st][p][r][kc], src + (size_t)(m0 + r) * CDIM + k0 + kc, v);
            }
        }
#pragma unroll
        for (int p = 0; p < 2; p++) {
            const __half* src = p ? Wl : Wh;
            int r = tid >> 2, kc = (tid & 3) * 8;
            cp_async16(&sB[st][p][r][kc], src + (size_t)(n0 + r) * CDIM + k0 + kc, true);
        }
        CP_COMMIT();
    };

    load_stage(0, 0);
    for (int kt = 0; kt < 12; kt++) {
        CP_WAIT0();
        __syncthreads();
        if (kt < 11) load_stage((kt + 1) & 1, (kt + 1) * 32);
        int st = kt & 1;
#pragma unroll
        for (int ks = 0; ks < 2; ks++) {
            wm::fragment<wm::matrix_a, 16, 16, 16, __half, wm::row_major> ah[2], al[2];
#pragma unroll
            for (int i = 0; i < 2; i++) {
                wm::load_matrix_sync(ah[i], &sA[st][0][wmi * 32 + i * 16][ks * 16], 40);
                wm::load_matrix_sync(al[i], &sA[st][1][wmi * 32 + i * 16][ks * 16], 40);
            }
#pragma unroll
            for (int j = 0; j < 2; j++) {
                wm::fragment<wm::matrix_b, 16, 16, 16, __half, wm::col_major> bh, bl;
                wm::load_matrix_sync(bh, &sB[st][0][wni * 32 + j * 16][ks * 16], 40);
                wm::load_matrix_sync(bl, &sB[st][1][wni * 32 + j * 16][ks * 16], 40);
                wm::mma_sync(acc[0][j], ah[0], bh, acc[0][j]);
                wm::mma_sync(acc[1][j], ah[1], bh, acc[1][j]);
                wm::mma_sync(acc[0][j], ah[0], bl, acc[0][j]);
                wm::mma_sync(acc[1][j], ah[1], bl, acc[1][j]);
                wm::mma_sync(acc[0][j], al[0], bh, acc[0][j]);
                wm::mma_sync(acc[1][j], al[1], bh, acc[1][j]);
            }
        }
    }

    __syncthreads();
    float (*Cs)[68] = reinterpret_cast<float(*)[68]>(&sA[0][0][0][0]);  // 128x68 fits in sA
#pragma unroll
    for (int i = 0; i < 2; i++)
#pragma unroll
        for (int j = 0; j < 2; j++)
            wm::store_matrix_sync(&Cs[wmi * 32 + i * 16][wni * 32 + j * 16], acc[i][j], 68,
                                  wm::mem_row_major);
    __syncthreads();
#pragma unroll
    for (int i = 0; i < 32; i++) {
        int e = i * 256 + tid;
        int r = e >> 6, cc = e & 63;
        int m = m0 + r, n = n0 + cc;
        if (m < M) {
            float val = Cs[r][cc];
            if (BIAS) val += bias[n];
            if (HEADSPLIT) {
                int b = m / Ttok, t = m % Ttok;
                size_t o = (((size_t)(b * NHEAD + (n0 >> 6)) * Ttok + t) << 6) + cc;
                split2(val, Yh[o], Yl[o]);
            } else {
                Yf[(size_t)m * CDIM + n] = val;
            }
        }
    }
}

// ---------------- attention: 64 queries x full 197 KV per CTA ----------------
__global__ __launch_bounds__(256)
void attn_kernel(const __half* __restrict__ Qh_, const __half* __restrict__ Ql_,
                 const __half* __restrict__ Kh_, const __half* __restrict__ Kl_,
                 const __half* __restrict__ Vh_, const __half* __restrict__ Vl_,
                 __half* __restrict__ Oh_, __half* __restrict__ Ol_)
{
    extern __shared__ char sm[];
    __half (*Qh)[72] = reinterpret_cast<__half(*)[72]>(sm);
    __half (*Ql)[72] = reinterpret_cast<__half(*)[72]>(sm + 9216);
    // KV stages: [st][plane] of 128x72 halves starting at 18432
    float (*S)[264]  = reinterpret_cast<float(*)[264]>(sm + 92160);   // 64x264
    __half (*Ph)[136] = reinterpret_cast<__half(*)[136]>(sm + 159744);
    __half (*Pl)[136] = reinterpret_cast<__half(*)[136]>(sm + 159744 + 17408);

    auto KV = [&](int st, int p) -> __half(*)[72] {
        return reinterpret_cast<__half(*)[72]>(sm + 18432 + (st * 2 + p) * 18432);
    };

    const int bh = blockIdx.y, q0 = blockIdx.x * 64;
    const __half* Qhp = Qh_ + (size_t)bh * TQ * HD;
    const __half* Qlp = Ql_ + (size_t)bh * TQ * HD;
    const __half* Khp = Kh_ + (size_t)bh * TKV * HD;
    const __half* Klp = Kl_ + (size_t)bh * TKV * HD;
    const __half* Vhp = Vh_ + (size_t)bh * TKV * HD;
    const __half* Vlp = Vl_ + (size_t)bh * TKV * HD;

    const int tid = threadIdx.x;
    const int wid = tid >> 5, lane = tid & 31;
    const int wmi = wid >> 2, wni = wid & 3;

    auto load_kv = [&](int st, int chunk, const __half* srch, const __half* srcl) {
#pragma unroll
        for (int p = 0; p < 2; p++) {
            const __half* src = p ? srcl : srch;
#pragma unroll
            for (int i = 0; i < 4; i++) {
                int c = i * 256 + tid;
                int r = c >> 3, cc = (c & 7) * 8;
                int t = chunk * 128 + r;
                cp_async16(&KV(st, p)[r][cc], src + (size_t)t * HD + cc, t < TKV);
            }
        }
        CP_COMMIT();
    };

    // prologue: Q (both planes) + K chunk 0 in one group
    {
#pragma unroll
        for (int p = 0; p < 2; p++) {
            const __half* src = p ? Qlp : Qhp;
            __half (*dst)[72] = p ? Ql : Qh;
#pragma unroll
            for (int i = 0; i < 2; i++) {
                int c = i * 256 + tid;
                int r = c >> 3, cc = (c & 7) * 8;
                int t = q0 + r;
                cp_async16(&dst[r][cc], src + (size_t)t * HD + cc, t < TQ);
            }
        }
#pragma unroll
        for (int p = 0; p < 2; p++) {
            const __half* src = p ? Klp : Khp;
#pragma unroll
            for (int i = 0; i < 4; i++) {
                int c = i * 256 + tid;
                int r = c >> 3, cc = (c & 7) * 8;
                cp_async16(&KV(0, p)[r][cc], src + (size_t)r * HD + cc, r < TKV);
            }
        }
        CP_COMMIT();
    }

    // ---- S = Q K^T over 2 chunks of 128 kv rows ----
    for (int kc = 0; kc < 2; kc++) {
        CP_WAIT0();
        __syncthreads();
        if (kc == 0) load_kv(1, 1, Khp, Klp);     // prefetch K chunk 1
        else         load_kv(0, 0, Vhp, Vlp);     // prefetch V chunk 0 (overlaps softmax)
        int st = kc;
        wm::fragment<wm::accumulator, 16, 16, 16, float> sa[2][2];
#pragma unroll
        for (int i = 0; i < 2; i++)
#pragma unroll
            for (int j = 0; j < 2; j++) wm::fill_fragment(sa[i][j], 0.f);
#pragma unroll
        for (int ks = 0; ks < 4; ks++) {
            wm::fragment<wm::matrix_a, 16, 16, 16, __half, wm::row_major> qh[2], ql[2];
#pragma unroll
            for (int i = 0; i < 2; i++) {
                wm::load_matrix_sync(qh[i], &Qh[wmi * 32 + i * 16][ks * 16], 72);
                wm::load_matrix_sync(ql[i], &Ql[wmi * 32 + i * 16][ks * 16], 72);
            }
#pragma unroll
            for (int j = 0; j < 2; j++) {
                wm::fragment<wm::matrix_b, 16, 16, 16, __half, wm::col_major> kh, kl;
                wm::load_matrix_sync(kh, &KV(st, 0)[wni * 32 + j * 16][ks * 16], 72);
                wm::load_matrix_sync(kl, &KV(st, 1)[wni * 32 + j * 16][ks * 16], 72);
                wm::mma_sync(sa[0][j], qh[0], kh, sa[0][j]);
                wm::mma_sync(sa[1][j], qh[1], kh, sa[1][j]);
                wm::mma_sync(sa[0][j], qh[0], kl, sa[0][j]);
                wm::mma_sync(sa[1][j], qh[1], kl, sa[1][j]);
                wm::mma_sync(sa[0][j], ql[0], kh, sa[0][j]);
                wm::mma_sync(sa[1][j], ql[1], kh, sa[1][j]);
            }
        }
#pragma unroll
        for (int i = 0; i < 2; i++)
#pragma unroll
            for (int j = 0; j < 2; j++)
                wm::store_matrix_sync(&S[wmi * 32 + i * 16][kc * 128 + wni * 32 + j * 16],
                                      sa[i][j], 264, wm::mem_row_major);
    }
    __syncthreads();

    // ---- softmax (fp32), 8 rows per warp ----
#pragma unroll
    for (int rr = 0; rr < 8; rr++) {
        int r = wid * 8 + rr;
        float mx = -1e30f;
        for (int j = lane; j < TKV; j += 32) mx = fmaxf(mx, S[r][j]);
#pragma unroll
        for (int o = 16; o; o >>= 1) mx = fmaxf(mx, __shfl_xor_sync(0xffffffffu, mx, o));
        float sum = 0.f;
        for (int j = lane; j < 264; j += 32) {
            float p = (j < TKV) ? __expf((S[r][j] - mx) * ATT_SCALE) : 0.f;
            S[r][j] = p;
            sum += p;
        }
#pragma unroll
        for (int o = 16; o; o >>= 1) sum += __shfl_xor_sync(0xffffffffu, sum, o);
        float inv = 1.f / sum;
        for (int j = lane; j < TKV; j += 32) S[r][j] *= inv;
    }
    __syncthreads();

    load_kv(1, 1, Vhp, Vlp);  // prefetch V chunk 1

    // ---- O = P V over 2 chunks of 128 ----
    wm::fragment<wm::accumulator, 16, 16, 16, float> oa[2];
    wm::fill_fragment(oa[0], 0.f);
    wm::fill_fragment(oa[1], 0.f);
    for (int kc = 0; kc < 2; kc++) {
        if (kc == 0) { CP_WAIT1(); } else { CP_WAIT0(); }
        __syncthreads();                 // V(kc) ready + previous MMA done
        // split P chunk kc (S cols [kc*128, kc*128+128), already zero-padded)
#pragma unroll
        for (int i = 0; i < 32; i++) {
            int e = i * 256 + tid;
            int r = e >> 7, cc = e & 127;
            split2(S[r][kc * 128 + cc], Ph[r][cc], Pl[r][cc]);
        }
        __syncthreads();
        int st = kc;
#pragma unroll
        for (int ks = 0; ks < 8; ks++) {
            wm::fragment<wm::matrix_a, 16, 16, 16, __half, wm::row_major> ph[2], pl[2];
#pragma unroll
            for (int i = 0; i < 2; i++) {
                wm::load_matrix_sync(ph[i], &Ph[wmi * 32 + i * 16][ks * 16], 136);
                wm::load_matrix_sync(pl[i], &Pl[wmi * 32 + i * 16][ks * 16], 136);
            }
            wm::fragment<wm::matrix_b, 16, 16, 16, __half, wm::row_major> vh, vl;
            wm::load_matrix_sync(vh, &KV(st, 0)[ks * 16][wni * 16], 72);
            wm::load_matrix_sync(vl, &KV(st, 1)[ks * 16][wni * 16], 72);
            wm::mma_sync(oa[0], ph[0], vh, oa[0]);
            wm::mma_sync(oa[1], ph[1], vh, oa[1]);
            wm::mma_sync(oa[0], ph[0], vl, oa[0]);
            wm::mma_sync(oa[1], ph[1], vl, oa[1]);
            wm::mma_sync(oa[0], pl[0], vh, oa[0]);
            wm::mma_sync(oa[1], pl[1], vh, oa[1]);
        }
    }
    __syncthreads();
    wm::store_matrix_sync(&S[wmi * 32][wni * 16], oa[0], 264, wm::mem_row_major);
    wm::store_matrix_sync(&S[wmi * 32 + 16][wni * 16], oa[1], 264, wm::mem_row_major);
    __syncthreads();

    const int b = bh / NHEAD, hh = bh % NHEAD;
#pragma unroll
    for (int i = 0; i < 16; i++) {
        int e = i * 256 + tid;
        int r = e >> 6, cc = e & 63;
        int t = q0 + r;
        if (t < TQ) {
            size_t o = ((size_t)(b * TQ + t)) * CDIM + hh * HD + cc;
            split2(S[r][cc], Oh_[o], Ol_[o]);
        }
    }
}

// ---------------- launch ----------------
extern "C" void kernel_launch(void* const* d_in, const int* in_sizes, int n_in,
                              void* d_out, int out_size)
{
    const float* x      = (const float*)d_in[0];
    const float* conv_w = (const float*)d_in[1];
    const float* gamma  = (const float*)d_in[2];
    const float* beta   = (const float*)d_in[3];
    const float* mean   = (const float*)d_in[4];
    const float* var    = (const float*)d_in[5];
    const float* w_q    = (const float*)d_in[6];
    const float* w_k    = (const float*)d_in[7];
    const float* w_v    = (const float*)d_in[8];
    const float* w_proj = (const float*)d_in[9];
    const float* b_proj = (const float*)d_in[10];
    float* out = (float*)d_out;

    __half *xqh, *xql, *xkh, *xkl, *xvh, *xvl, *qh, *ql, *kh, *kl, *vh, *vl, *ath, *atl, *wh, *wl;
    cudaGetSymbolAddress((void**)&xqh, g_xqh); cudaGetSymbolAddress((void**)&xql, g_xql);
    cudaGetSymbolAddress((void**)&xkh, g_xkh); cudaGetSymbolAddress((void**)&xkl, g_xkl);
    cudaGetSymbolAddress((void**)&xvh, g_xvh); cudaGetSymbolAddress((void**)&xvl, g_xvl);
    cudaGetSymbolAddress((void**)&qh,  g_qh);  cudaGetSymbolAddress((void**)&ql,  g_ql);
    cudaGetSymbolAddress((void**)&kh,  g_kh);  cudaGetSymbolAddress((void**)&kl,  g_kl);
    cudaGetSymbolAddress((void**)&vh,  g_vh);  cudaGetSymbolAddress((void**)&vl,  g_vl);
    cudaGetSymbolAddress((void**)&ath, g_ath); cudaGetSymbolAddress((void**)&atl, g_atl);
    cudaGetSymbolAddress((void**)&wh,  g_wh);  cudaGetSymbolAddress((void**)&wl,  g_wl);

    const int WN = CDIM * CDIM;  // 147456
    split_w_kernel<<<WN / 256, 256>>>(w_q,    wh,          wl,          WN);
    split_w_kernel<<<WN / 256, 256>>>(w_k,    wh + WN,     wl + WN,     WN);
    split_w_kernel<<<WN / 256, 256>>>(w_v,    wh + 2*WN,   wl + 2*WN,   WN);
    split_w_kernel<<<WN / 256, 256>>>(w_proj, wh + 3*WN,   wl + 3*WN,   WN);

    conv_bn_kernel<<<(BATCH * TQ * CDIM) / 256, 256>>>(
        x, conv_w, gamma, beta, mean, var, xqh, xql, 28, 1);
    conv_bn_kernel<<<(BATCH * TKV * CDIM) / 256, 256>>>(
        x, conv_w + CDIM * 9, gamma + CDIM, beta + CDIM, mean + CDIM, var + CDIM,
        xkh, xkl, 14, 2);
    conv_bn_kernel<<<(BATCH * TKV * CDIM) / 256, 256>>>(
        x, conv_w + 2 * CDIM * 9, gamma + 2 * CDIM, beta + 2 * CDIM, mean + 2 * CDIM,
        var + 2 * CDIM, xvh, xvl, 14, 2);

    const int MQ = BATCH * TQ;    // 25120
    const int MKV = BATCH * TKV;  // 6304
    dim3 gq((MQ + 127) / 128, 6), gkv((MKV + 127) / 128, 6);
    gemm_half_kernel<true, false><<<gq, 256>>>(xqh, xql, wh, wl, nullptr,
                                               nullptr, qh, ql, MQ, TQ);
    gemm_half_kernel<true, false><<<gkv, 256>>>(xkh, xkl, wh + WN, wl + WN, nullptr,
                                                nullptr, kh, kl, MKV, TKV);
    gemm_half_kernel<true, false><<<gkv, 256>>>(xvh, xvl, wh + 2*WN, wl + 2*WN, nullptr,
                                                nullptr, vh, vl, MKV, TKV);

    const int ATT_SMEM = 194560;
    cudaFuncSetAttribute(attn_kernel, cudaFuncAttributeMaxDynamicSharedMemorySize, ATT_SMEM);
    attn_kernel<<<dim3((TQ + 63) / 64, BATCH * NHEAD), 256, ATT_SMEM>>>(
        qh, ql, kh, kl, vh, vl, ath, atl);

    gemm_half_kernel<false, true><<<gq, 256>>>(ath, atl, wh + 3*WN, wl + 3*WN, b_proj,
                                               out, nullptr, nullptr, MQ, TQ);
}

// round 6
// speedup vs baseline: 1.7503x; 1.1167x over previous
#include <cuda_runtime.h>
#include <cuda_fp16.h>
#include <mma.h>
#include <cstdint>

namespace wm = nvcuda::wmma;

#define BATCH 32
#define HIMG 28
#define CDIM 384
#define TQ 785
#define TKV 197
#define NHEAD 6
#define HD 64
#define ATT_SCALE 0.051031036307982884f  /* 1/sqrt(384) -- DIM, not head_dim */

// ---------------- persistent planes (no allocation) ----------------
__device__ __half g_xqh[BATCH*TQ*CDIM],  g_xql[BATCH*TQ*CDIM];
__device__ __half g_xkh[BATCH*TKV*CDIM], g_xkl[BATCH*TKV*CDIM];
__device__ __half g_xvh[BATCH*TKV*CDIM], g_xvl[BATCH*TKV*CDIM];
__device__ __half g_q[BATCH*TQ*CDIM];    // [b][h][t][64] single plane
__device__ __half g_k[BATCH*TKV*CDIM];
__device__ __half g_v[BATCH*TKV*CDIM];
__device__ __half g_ath[BATCH*TQ*CDIM],  g_atl[BATCH*TQ*CDIM];  // O split
__device__ __half g_wh[4*CDIM*CDIM],     g_wl[4*CDIM*CDIM];

__device__ __forceinline__ void split2(float v, __half& hi, __half& lo) {
    __half h = __float2half_rn(v);
    hi = h;
    lo = __float2half_rn(v - __half2float(h));
}

__device__ __forceinline__ void cp_async16(void* sdst, const void* gsrc, bool pred) {
    unsigned int s = (unsigned int)__cvta_generic_to_shared(sdst);
    int bytes = pred ? 16 : 0;
    asm volatile("cp.async.cg.shared.global [%0], [%1], 16, %2;\n"
                 :: "r"(s), "l"(gsrc), "r"(bytes));
}
#define CP_COMMIT() asm volatile("cp.async.commit_group;\n" ::: "memory")
#define CP_WAIT0()  asm volatile("cp.async.wait_group 0;\n" ::: "memory")
#define CP_WAIT1()  asm volatile("cp.async.wait_group 1;\n" ::: "memory")

// ---------------- all 4 weight splits in one launch ----------------
__global__ void split_w_all(const float* __restrict__ w0, const float* __restrict__ w1,
                            const float* __restrict__ w2, const float* __restrict__ w3,
                            __half* __restrict__ h, __half* __restrict__ l)
{
    const int WN = CDIM * CDIM;
    int i = blockIdx.x * blockDim.x + threadIdx.x;
    if (i >= 4 * WN) return;
    int sel = i / WN, off = i - sel * WN;
    const float* src = sel == 0 ? w0 : sel == 1 ? w1 : sel == 2 ? w2 : w3;
    split2(src[off], h[i], l[i]);
}

// ---------------- depthwise conv3x3 + BN -> split halves ----------------
__global__ void conv_bn_kernel(const float* __restrict__ x,
                               const float* __restrict__ cw,
                               const float* __restrict__ gamma,
                               const float* __restrict__ beta,
                               const float* __restrict__ mean,
                               const float* __restrict__ var,
                               __half* __restrict__ outh, __half* __restrict__ outl,
                               int Hout, int stride)
{
    int idx = blockIdx.x * blockDim.x + threadIdx.x;
    int Tout = Hout * Hout + 1;
    int c = idx % CDIM;
    int t = (idx / CDIM) % Tout;
    int b = idx / (CDIM * Tout);
    if (b >= BATCH) return;

    float val;
    if (t == 0) {
        val = x[(size_t)(b * TQ) * CDIM + c];
    } else {
        int p = t - 1;
        int oi = p / Hout, oj = p % Hout;
        float inv  = gamma[c] * rsqrtf(var[c] + 1e-5f);
        float bias = beta[c] - mean[c] * inv;
        float acc = 0.f;
#pragma unroll
        for (int ky = 0; ky < 3; ky++) {
            int iy = oi * stride + ky - 1;
            if (iy < 0 || iy >= HIMG) continue;
#pragma unroll
            for (int kx = 0; kx < 3; kx++) {
                int ix = oj * stride + kx - 1;
                if (ix < 0 || ix >= HIMG) continue;
                acc += cw[c * 9 + ky * 3 + kx] *
                       x[(size_t)(b * TQ + 1 + iy * HIMG + ix) * CDIM + c];
            }
        }
        val = acc * inv + bias;
    }
    split2(val, outh[idx], outl[idx]);
}

// ---------------- split-half GEMM: Y[m][n] = sum_k X[m][k]*W[n][k] ----------------
// CTA 128x128, K-step 32, cp.async double-buffered, 256 threads, warp tile 32x64.
template <bool HEADSPLIT, bool BIAS>
__global__ __launch_bounds__(256, 2)
void gemm_half_kernel(const __half* __restrict__ Xh, const __half* __restrict__ Xl,
                      const __half* __restrict__ Wh, const __half* __restrict__ Wl,
                      const float* __restrict__ bias,
                      float* __restrict__ Yf, __half* __restrict__ Yh,
                      int M, int Ttok)
{
    __shared__ __half sA[2][2][128][40];
    __shared__ __half sB[2][2][128][40];

    const int m0 = blockIdx.x * 128, n0 = blockIdx.y * 128;
    const int tid = threadIdx.x, wid = tid >> 5;
    const int wmi = wid >> 1, wni = wid & 1;   // 4 x 2 warps -> warp tile 32x64

    wm::fragment<wm::accumulator, 16, 16, 16, float> acc[2][4];
#pragma unroll
    for (int i = 0; i < 2; i++)
#pragma unroll
        for (int j = 0; j < 4; j++) wm::fill_fragment(acc[i][j], 0.f);

    auto load_stage = [&](int st, int k0) {
#pragma unroll
        for (int p = 0; p < 2; p++) {
            const __half* src = p ? Xl : Xh;
#pragma unroll
            for (int i = 0; i < 2; i++) {
                int c = i * 256 + tid;
                int r = c >> 2, kc = (c & 3) * 8;
                cp_async16(&sA[st][p][r][kc], src + (size_t)(m0 + r) * CDIM + k0 + kc,
                           (m0 + r) < M);
            }
        }
#pragma unroll
        for (int p = 0; p < 2; p++) {
            const __half* src = p ? Wl : Wh;
#pragma unroll
            for (int i = 0; i < 2; i++) {
                int c = i * 256 + tid;
                int r = c >> 2, kc = (c & 3) * 8;
                cp_async16(&sB[st][p][r][kc], src + (size_t)(n0 + r) * CDIM + k0 + kc, true);
            }
        }
        CP_COMMIT();
    };

    load_stage(0, 0);
    for (int kt = 0; kt < 12; kt++) {
        CP_WAIT0();
        __syncthreads();
        if (kt < 11) load_stage((kt + 1) & 1, (kt + 1) * 32);
        int st = kt & 1;
#pragma unroll
        for (int ks = 0; ks < 2; ks++) {
            wm::fragment<wm::matrix_a, 16, 16, 16, __half, wm::row_major> ah[2], al[2];
#pragma unroll
            for (int i = 0; i < 2; i++) {
                wm::load_matrix_sync(ah[i], &sA[st][0][wmi * 32 + i * 16][ks * 16], 40);
                wm::load_matrix_sync(al[i], &sA[st][1][wmi * 32 + i * 16][ks * 16], 40);
            }
#pragma unroll
            for (int j = 0; j < 4; j++) {
                wm::fragment<wm::matrix_b, 16, 16, 16, __half, wm::col_major> bh, bl;
                wm::load_matrix_sync(bh, &sB[st][0][wni * 64 + j * 16][ks * 16], 40);
                wm::load_matrix_sync(bl, &sB[st][1][wni * 64 + j * 16][ks * 16], 40);
#pragma unroll
                for (int i = 0; i < 2; i++) {
                    wm::mma_sync(acc[i][j], ah[i], bh, acc[i][j]);
                    wm::mma_sync(acc[i][j], ah[i], bl, acc[i][j]);
                    wm::mma_sync(acc[i][j], al[i], bh, acc[i][j]);
                }
            }
        }
    }

    __syncthreads();
    float (*Cs)[132] = reinterpret_cast<float(*)[132]>(&sA[0][0][0][0]);  // 128x132 = 67.6KB
#pragma unroll
    for (int i = 0; i < 2; i++)
#pragma unroll
        for (int j = 0; j < 4; j++)
            wm::store_matrix_sync(&Cs[wmi * 32 + i * 16][wni * 64 + j * 16], acc[i][j], 132,
                                  wm::mem_row_major);
    __syncthreads();
#pragma unroll
    for (int i = 0; i < 64; i++) {
        int e = i * 256 + tid;
        int r = e >> 7, cc = e & 127;
        int m = m0 + r, n = n0 + cc;
        if (m < M) {
            float val = Cs[r][cc];
            if (BIAS) val += bias[n];
            if (HEADSPLIT) {
                int b = m / Ttok, t = m % Ttok;
                size_t o = (((size_t)(b * NHEAD + (n >> 6)) * Ttok + t) << 6) + (n & 63);
                Yh[o] = __float2half_rn(val);
            } else {
                Yf[(size_t)m * CDIM + n] = val;
            }
        }
    }
}

// ---------------- attention: 128 queries x full 197 KV per CTA, fp16 single-plane ----------------
// smem: Qs half[128][72] @0 | KVs half[2][128][72] @18432 | S float[128][256] @55296
//       P half[128][136] @186368   -> total 221184
__global__ __launch_bounds__(256)
void attn_kernel(const __half* __restrict__ Q_, const __half* __restrict__ K_,
                 const __half* __restrict__ V_,
                 __half* __restrict__ Oh_, __half* __restrict__ Ol_)
{
    extern __shared__ char sm[];
    __half (*Qs)[72] = reinterpret_cast<__half(*)[72]>(sm);
    float (*S)[256]  = reinterpret_cast<float(*)[256]>(sm + 55296);
    __half (*P)[136] = reinterpret_cast<__half(*)[136]>(sm + 186368);
    auto KVs = [&](int st) -> __half(*)[72] {
        return reinterpret_cast<__half(*)[72]>(sm + 18432 + st * 18432);
    };

    const int bh = blockIdx.y, q0 = blockIdx.x * 128;
    const __half* Qp = Q_ + (size_t)bh * TQ * HD;
    const __half* Kp = K_ + (size_t)bh * TKV * HD;
    const __half* Vp = V_ + (size_t)bh * TKV * HD;

    const int tid = threadIdx.x;
    const int wid = tid >> 5, lane = tid & 31;
    const int wmi = wid >> 2, wni = wid & 3;   // S phase: 2 x 4
    const int pmi = wid >> 1, pni = wid & 1;   // PV phase: 4 x 2

    auto load_kv = [&](int st, int chunk, const __half* src) {
#pragma unroll
        for (int i = 0; i < 4; i++) {
            int c = i * 256 + tid;
            int r = c >> 3, cc = (c & 7) * 8;
            int t = chunk * 128 + r;
            cp_async16(&KVs(st)[r][cc], src + (size_t)t * HD + cc, t < TKV);
        }
        CP_COMMIT();
    };

    // prologue: group A = Q + K chunk0 ; group B = K chunk1
    {
#pragma unroll
        for (int i = 0; i < 4; i++) {
            int c = i * 256 + tid;
            int r = c >> 3, cc = (c & 7) * 8;
            cp_async16(&Qs[r][cc], Qp + (size_t)(q0 + r) * HD + cc, (q0 + r) < TQ);
        }
#pragma unroll
        for (int i = 0; i < 4; i++) {
            int c = i * 256 + tid;
            int r = c >> 3, cc = (c & 7) * 8;
            cp_async16(&KVs(0)[r][cc], Kp + (size_t)r * HD + cc, true);  // rows 0..127 < 197
        }
        CP_COMMIT();
        load_kv(1, 1, Kp);  // group B
    }

    // ---- S = Q K^T : 2 chunks of 128 kv cols ----
    for (int kc = 0; kc < 2; kc++) {
        if (kc == 0) { CP_WAIT1(); } else { CP_WAIT1(); }
        __syncthreads();
        wm::fragment<wm::accumulator, 16, 16, 16, float> sa[4][2];
#pragma unroll
        for (int i = 0; i < 4; i++)
#pragma unroll
            for (int j = 0; j < 2; j++) wm::fill_fragment(sa[i][j], 0.f);
#pragma unroll
        for (int ks = 0; ks < 4; ks++) {
            wm::fragment<wm::matrix_a, 16, 16, 16, __half, wm::row_major> qa[4];
#pragma unroll
            for (int i = 0; i < 4; i++)
                wm::load_matrix_sync(qa[i], &Qs[wmi * 64 + i * 16][ks * 16], 72);
#pragma unroll
            for (int j = 0; j < 2; j++) {
                wm::fragment<wm::matrix_b, 16, 16, 16, __half, wm::col_major> kb;
                wm::load_matrix_sync(kb, &KVs(kc)[wni * 32 + j * 16][ks * 16], 72);
#pragma unroll
                for (int i = 0; i < 4; i++) wm::mma_sync(sa[i][j], qa[i], kb, sa[i][j]);
            }
        }
#pragma unroll
        for (int i = 0; i < 4; i++)
#pragma unroll
            for (int j = 0; j < 2; j++)
                wm::store_matrix_sync(&S[wmi * 64 + i * 16][kc * 128 + wni * 32 + j * 16],
                                      sa[i][j], 256, wm::mem_row_major);
        __syncthreads();                       // K chunk consumed
        load_kv(kc, kc, Vp);                   // group C (V0) / group D (V1)
    }

    // ---- softmax (fp32), 16 rows per warp; overlaps V0 load ----
#pragma unroll
    for (int rr = 0; rr < 16; rr++) {
        int r = wid * 16 + rr;
        float mx = -1e30f;
        for (int j = lane; j < TKV; j += 32) mx = fmaxf(mx, S[r][j]);
#pragma unroll
        for (int o = 16; o; o >>= 1) mx = fmaxf(mx, __shfl_xor_sync(0xffffffffu, mx, o));
        float sum = 0.f;
        for (int j = lane; j < 256; j += 32) {
            float p = (j < TKV) ? __expf((S[r][j] - mx) * ATT_SCALE) : 0.f;
            S[r][j] = p;
            sum += p;
        }
#pragma unroll
        for (int o = 16; o; o >>= 1) sum += __shfl_xor_sync(0xffffffffu, sum, o);
        float inv = 1.f / sum;
        for (int j = lane; j < TKV; j += 32) S[r][j] *= inv;
    }
    __syncthreads();

    // ---- O = P V : 2 chunks of 128 ----
    wm::fragment<wm::accumulator, 16, 16, 16, float> oa[2][2];
#pragma unroll
    for (int i = 0; i < 2; i++)
#pragma unroll
        for (int j = 0; j < 2; j++) wm::fill_fragment(oa[i][j], 0.f);
    for (int kc = 0; kc < 2; kc++) {
        // convert P chunk (S already zeroed for cols >= TKV)
#pragma unroll
        for (int i = 0; i < 64; i++) {
            int e = i * 256 + tid;
            int r = e >> 7, cc = e & 127;
            P[r][cc] = __float2half_rn(S[r][kc * 128 + cc]);
        }
        if (kc == 0) { CP_WAIT1(); } else { CP_WAIT0(); }
        __syncthreads();                       // V(kc) + P ready
#pragma unroll
        for (int ks = 0; ks < 8; ks++) {
            wm::fragment<wm::matrix_a, 16, 16, 16, __half, wm::row_major> pa[2];
#pragma unroll
            for (int i = 0; i < 2; i++)
                wm::load_matrix_sync(pa[i], &P[pmi * 32 + i * 16][ks * 16], 136);
#pragma unroll
            for (int j = 0; j < 2; j++) {
                wm::fragment<wm::matrix_b, 16, 16, 16, __half, wm::row_major> vb;
                wm::load_matrix_sync(vb, &KVs(kc)[ks * 16][pni * 32 + j * 16], 72);
#pragma unroll
                for (int i = 0; i < 2; i++) wm::mma_sync(oa[i][j], pa[i], vb, oa[i][j]);
            }
        }
        __syncthreads();                       // P consumed before overwrite
    }
#pragma unroll
    for (int i = 0; i < 2; i++)
#pragma unroll
        for (int j = 0; j < 2; j++)
            wm::store_matrix_sync(&S[pmi * 32 + i * 16][pni * 32 + j * 16], oa[i][j], 256,
                                  wm::mem_row_major);
    __syncthreads();

    const int b = bh / NHEAD, hh = bh % NHEAD;
#pragma unroll
    for (int i = 0; i < 32; i++) {
        int e = i * 256 + tid;
        int r = e >> 6, cc = e & 63;
        int t = q0 + r;
        if (t < TQ) {
            size_t o = ((size_t)(b * TQ + t)) * CDIM + hh * HD + cc;
            split2(S[r][cc], Oh_[o], Ol_[o]);
        }
    }
}

// ---------------- launch ----------------
extern "C" void kernel_launch(void* const* d_in, const int* in_sizes, int n_in,
                              void* d_out, int out_size)
{
    const float* x      = (const float*)d_in[0];
    const float* conv_w = (const float*)d_in[1];
    const float* gamma  = (const float*)d_in[2];
    const float* beta   = (const float*)d_in[3];
    const float* mean   = (const float*)d_in[4];
    const float* var    = (const float*)d_in[5];
    const float* w_q    = (const float*)d_in[6];
    const float* w_k    = (const float*)d_in[7];
    const float* w_v    = (const float*)d_in[8];
    const float* w_proj = (const float*)d_in[9];
    const float* b_proj = (const float*)d_in[10];
    float* out = (float*)d_out;

    __half *xqh, *xql, *xkh, *xkl, *xvh, *xvl, *q, *k, *v, *ath, *atl, *wh, *wl;
    cudaGetSymbolAddress((void**)&xqh, g_xqh); cudaGetSymbolAddress((void**)&xql, g_xql);
    cudaGetSymbolAddress((void**)&xkh, g_xkh); cudaGetSymbolAddress((void**)&xkl, g_xkl);
    cudaGetSymbolAddress((void**)&xvh, g_xvh); cudaGetSymbolAddress((void**)&xvl, g_xvl);
    cudaGetSymbolAddress((void**)&q,   g_q);   cudaGetSymbolAddress((void**)&k,   g_k);
    cudaGetSymbolAddress((void**)&v,   g_v);
    cudaGetSymbolAddress((void**)&ath, g_ath); cudaGetSymbolAddress((void**)&atl, g_atl);
    cudaGetSymbolAddress((void**)&wh,  g_wh);  cudaGetSymbolAddress((void**)&wl,  g_wl);

    const int WN = CDIM * CDIM;  // 147456
    split_w_all<<<(4 * WN) / 256, 256>>>(w_q, w_k, w_v, w_proj, wh, wl);

    conv_bn_kernel<<<(BATCH * TQ * CDIM) / 256, 256>>>(
        x, conv_w, gamma, beta, mean, var, xqh, xql, 28, 1);
    conv_bn_kernel<<<(BATCH * TKV * CDIM) / 256, 256>>>(
        x, conv_w + CDIM * 9, gamma + CDIM, beta + CDIM, mean + CDIM, var + CDIM,
        xkh, xkl, 14, 2);
    conv_bn_kernel<<<(BATCH * TKV * CDIM) / 256, 256>>>(
        x, conv_w + 2 * CDIM * 9, gamma + 2 * CDIM, beta + 2 * CDIM, mean + 2 * CDIM,
        var + 2 * CDIM, xvh, xvl, 14, 2);

    const int MQ = BATCH * TQ;    // 25120
    const int MKV = BATCH * TKV;  // 6304
    dim3 gq((MQ + 127) / 128, 3), gkv((MKV + 127) / 128, 3);
    gemm_half_kernel<true, false><<<gq, 256>>>(xqh, xql, wh, wl, nullptr,
                                               nullptr, q, MQ, TQ);
    gemm_half_kernel<true, false><<<gkv, 256>>>(xkh, xkl, wh + WN, wl + WN, nullptr,
                                                nullptr, k, MKV, TKV);
    gemm_half_kernel<true, false><<<gkv, 256>>>(xvh, xvl, wh + 2*WN, wl + 2*WN, nullptr,
                                                nullptr, v, MKV, TKV);

    const int ATT_SMEM = 221184;
    cudaFuncSetAttribute(attn_kernel, cudaFuncAttributeMaxDynamicSharedMemorySize, ATT_SMEM);
    attn_kernel<<<dim3((TQ + 127) / 128, BATCH * NHEAD), 256, ATT_SMEM>>>(
        q, k, v, ath, atl);

    gemm_half_kernel<false, true><<<gq, 256>>>(ath, atl, wh + 3*WN, wl + 3*WN, b_proj,
                                               out, nullptr, MQ, TQ);
}

// round 13
// speedup vs baseline: 2.0636x; 1.1790x over previous
#include <cuda_runtime.h>
#include <cuda_fp16.h>
#include <mma.h>
#include <cstdint>

namespace wm = nvcuda::wmma;

#define BATCH 32
#define HIMG 28
#define CDIM 384
#define TQ 785
#define TKV 197
#define NHEAD 6
#define HD 64
#define ATT_SCALE 0.051031036307982884f  /* 1/sqrt(384) -- DIM, not head_dim */

// ---------------- persistent planes (no allocation) ----------------
__device__ __half g_xq[BATCH*TQ*CDIM];     // conv outputs, single fp16 plane
__device__ __half g_xk[BATCH*TKV*CDIM];
__device__ __half g_xv[BATCH*TKV*CDIM];
__device__ __half g_q[BATCH*TQ*CDIM];      // [b][h][t][64]
__device__ __half g_k[BATCH*TKV*CDIM];
__device__ __half g_v[BATCH*TKV*CDIM];
__device__ __half g_at[BATCH*TQ*CDIM];     // attention out, single plane [b][t][384]
__device__ __half g_wh[4*CDIM*CDIM], g_wl[4*CDIM*CDIM];  // weights split hi/lo

__device__ __forceinline__ void split2(float v, __half& hi, __half& lo) {
    __half h = __float2half_rn(v);
    hi = h;
    lo = __float2half_rn(v - __half2float(h));
}

__device__ __forceinline__ void cp_async16(void* sdst, const void* gsrc, bool pred) {
    unsigned int s = (unsigned int)__cvta_generic_to_shared(sdst);
    int bytes = pred ? 16 : 0;
    asm volatile("cp.async.cg.shared.global [%0], [%1], 16, %2;\n"
                 :: "r"(s), "l"(gsrc), "r"(bytes));
}
#define CP_COMMIT() asm volatile("cp.async.commit_group;\n" ::: "memory")
#define CP_WAIT0()  asm volatile("cp.async.wait_group 0;\n" ::: "memory")
#define CP_WAIT1()  asm volatile("cp.async.wait_group 1;\n" ::: "memory")

// ---------------- all 4 weight splits in one launch ----------------
__global__ void split_w_all(const float* __restrict__ w0, const float* __restrict__ w1,
                            const float* __restrict__ w2, const float* __restrict__ w3,
                            __half* __restrict__ h, __half* __restrict__ l)
{
    const int WN = CDIM * CDIM;
    int i = blockIdx.x * blockDim.x + threadIdx.x;
    if (i >= 4 * WN) return;
    int sel = i / WN, off = i - sel * WN;
    const float* src = sel == 0 ? w0 : sel == 1 ? w1 : sel == 2 ? w2 : w3;
    split2(src[off], h[i], l[i]);
}

// ---------------- depthwise conv3x3 + BN -> single fp16 plane ----------------
// grid (CDIM/128, ceil(Tout/32), BATCH), block 128. Weights staged in smem.
template <int HOUT, int STRIDE>
__global__ void conv_bn_kernel(const float* __restrict__ x,
                               const float* __restrict__ cw,
                               const float* __restrict__ gamma,
                               const float* __restrict__ beta,
                               const float* __restrict__ mean,
                               const float* __restrict__ var,
                               __half* __restrict__ out)
{
    __shared__ float sw[128 * 9];
    const int Tout = HOUT * HOUT + 1;
    const int c0 = blockIdx.x * 128;
    const int c = c0 + threadIdx.x;
    const int b = blockIdx.z;
    const int t0 = blockIdx.y * 32;

    for (int i = threadIdx.x; i < 128 * 9; i += 128) sw[i] = cw[c0 * 9 + i];
    float inv  = gamma[c] * rsqrtf(var[c] + 1e-5f);
    float bias = beta[c] - mean[c] * inv;
    __syncthreads();
    const float* wr = &sw[threadIdx.x * 9];

    for (int tt = 0; tt < 32; tt++) {
        int t = t0 + tt;
        if (t >= Tout) break;
        float val;
        if (t == 0) {
            val = x[(size_t)(b * TQ) * CDIM + c];
        } else {
            int p = t - 1;
            int oi = p / HOUT, oj = p % HOUT;   // compile-time HOUT -> mul/shift
            float acc = 0.f;
#pragma unroll
            for (int ky = 0; ky < 3; ky++) {
                int iy = oi * STRIDE + ky - 1;
                if (iy < 0 || iy >= HIMG) continue;
#pragma unroll
                for (int kx = 0; kx < 3; kx++) {
                    int ix = oj * STRIDE + kx - 1;
                    if (ix < 0 || ix >= HIMG) continue;
                    acc += wr[ky * 3 + kx] *
                           x[(size_t)(b * TQ + 1 + iy * HIMG + ix) * CDIM + c];
                }
            }
            val = acc * inv + bias;
        }
        out[((size_t)(b * Tout + t)) * CDIM + c] = __float2half_rn(val);
    }
}

// ---------------- GEMM: Y[m][n] = sum_k X[m][k]*(Wh+Wl)[n][k] ----------------
// X single fp16 plane; 2 MMAs per tile-pair. CTA 128x128, K-step 32, double-buffered.
// Dynamic smem overlaid: mainloop sA(20480)+sB(40960)=61440; epilogue Cs 128x136 f32=69632.
template <bool HEADSPLIT, bool BIAS>
__global__ __launch_bounds__(256)
void gemm_half_kernel(const __half* __restrict__ X,
                      const __half* __restrict__ Wh, const __half* __restrict__ Wl,
                      const float* __restrict__ bias,
                      float* __restrict__ Yf, __half* __restrict__ Yh,
                      int M, int Ttok)
{
    extern __shared__ char smraw[];
    __half (*sA)[128][40]    = reinterpret_cast<__half(*)[128][40]>(smraw);
    __half (*sB)[2][128][40] = reinterpret_cast<__half(*)[2][128][40]>(smraw + 20480);

    const int m0 = blockIdx.x * 128, n0 = blockIdx.y * 128;
    const int tid = threadIdx.x, wid = tid >> 5;
    const int wmi = wid >> 1, wni = wid & 1;   // 4 x 2 warps -> warp tile 32x64

    wm::fragment<wm::accumulator, 16, 16, 16, float> acc[2][4];
#pragma unroll
    for (int i = 0; i < 2; i++)
#pragma unroll
        for (int j = 0; j < 4; j++) wm::fill_fragment(acc[i][j], 0.f);

    auto load_stage = [&](int st, int k0) {
#pragma unroll
        for (int i = 0; i < 2; i++) {
            int c = i * 256 + tid;
            int r = c >> 2, kc = (c & 3) * 8;
            cp_async16(&sA[st][r][kc], X + (size_t)(m0 + r) * CDIM + k0 + kc, (m0 + r) < M);
        }
#pragma unroll
        for (int p = 0; p < 2; p++) {
            const __half* src = p ? Wl : Wh;
#pragma unroll
            for (int i = 0; i < 2; i++) {
                int c = i * 256 + tid;
                int r = c >> 2, kc = (c & 3) * 8;
                cp_async16(&sB[st][p][r][kc], src + (size_t)(n0 + r) * CDIM + k0 + kc, true);
            }
        }
        CP_COMMIT();
    };

    load_stage(0, 0);
    for (int kt = 0; kt < 12; kt++) {
        CP_WAIT0();
        __syncthreads();
        if (kt < 11) load_stage((kt + 1) & 1, (kt + 1) * 32);
        int st = kt & 1;
#pragma unroll
        for (int ks = 0; ks < 2; ks++) {
            wm::fragment<wm::matrix_a, 16, 16, 16, __half, wm::row_major> ah[2];
#pragma unroll
            for (int i = 0; i < 2; i++)
                wm::load_matrix_sync(ah[i], &sA[st][wmi * 32 + i * 16][ks * 16], 40);
#pragma unroll
            for (int j = 0; j < 4; j++) {
                wm::fragment<wm::matrix_b, 16, 16, 16, __half, wm::col_major> bh, bl;
                wm::load_matrix_sync(bh, &sB[st][0][wni * 64 + j * 16][ks * 16], 40);
                wm::load_matrix_sync(bl, &sB[st][1][wni * 64 + j * 16][ks * 16], 40);
#pragma unroll
                for (int i = 0; i < 2; i++) {
                    wm::mma_sync(acc[i][j], ah[i], bh, acc[i][j]);
                    wm::mma_sync(acc[i][j], ah[i], bl, acc[i][j]);
                }
            }
        }
    }

    __syncthreads();
    float (*Cs)[136] = reinterpret_cast<float(*)[136]>(smraw);
#pragma unroll
    for (int i = 0; i < 2; i++)
#pragma unroll
        for (int j = 0; j < 4; j++)
            wm::store_matrix_sync(&Cs[wmi * 32 + i * 16][wni * 64 + j * 16], acc[i][j], 136,
                                  wm::mem_row_major);
    __syncthreads();
#pragma unroll
    for (int i = 0; i < 64; i++) {
        int e = i * 256 + tid;
        int r = e >> 7, cc = e & 127;
        int m = m0 + r, n = n0 + cc;
        if (m < M) {
            float val = Cs[r][cc];
            if (BIAS) val += bias[n];
            if (HEADSPLIT) {
                int b = m / Ttok, t = m % Ttok;
                size_t o = (((size_t)(b * NHEAD + (n >> 6)) * Ttok + t) << 6) + (n & 63);
                Yh[o] = __float2half_rn(val);
            } else {
                Yf[(size_t)m * CDIM + n] = val;
            }
        }
    }
}

// ---------------- attention: 128 queries x full 197 KV per CTA, 256 threads ----------------
// EXACT body that passed at 579.6us; only the epilogue now writes a single fp16 plane.
// smem: Qs half[128][72] @0 | KVs half[2][128][72] @18432 | S float[128][256] @55296
//       P half[128][136] @186368   -> total 221184
__global__ __launch_bounds__(256)
void attn_kernel(const __half* __restrict__ Q_, const __half* __restrict__ K_,
                 const __half* __restrict__ V_, __half* __restrict__ O_)
{
    extern __shared__ char sm[];
    __half (*Qs)[72] = reinterpret_cast<__half(*)[72]>(sm);
    float (*S)[256]  = reinterpret_cast<float(*)[256]>(sm + 55296);
    __half (*P)[136] = reinterpret_cast<__half(*)[136]>(sm + 186368);
    auto KVs = [&](int st) -> __half(*)[72] {
        return reinterpret_cast<__half(*)[72]>(sm + 18432 + st * 18432);
    };

    const int bh = blockIdx.y, q0 = blockIdx.x * 128;
    const __half* Qp = Q_ + (size_t)bh * TQ * HD;
    const __half* Kp = K_ + (size_t)bh * TKV * HD;
    const __half* Vp = V_ + (size_t)bh * TKV * HD;

    const int tid = threadIdx.x;
    const int wid = tid >> 5, lane = tid & 31;
    const int wmi = wid >> 2, wni = wid & 3;   // S phase: 2 x 4
    const int pmi = wid >> 1, pni = wid & 1;   // PV phase: 4 x 2

    auto load_kv = [&](int st, int chunk, const __half* src) {
#pragma unroll
        for (int i = 0; i < 4; i++) {
            int c = i * 256 + tid;
            int r = c >> 3, cc = (c & 7) * 8;
            int t = chunk * 128 + r;
            cp_async16(&KVs(st)[r][cc], src + (size_t)t * HD + cc, t < TKV);
        }
        CP_COMMIT();
    };

    // prologue: group A = Q + K chunk0 ; group B = K chunk1
    {
#pragma unroll
        for (int i = 0; i < 4; i++) {
            int c = i * 256 + tid;
            int r = c >> 3, cc = (c & 7) * 8;
            cp_async16(&Qs[r][cc], Qp + (size_t)(q0 + r) * HD + cc, (q0 + r) < TQ);
        }
#pragma unroll
        for (int i = 0; i < 4; i++) {
            int c = i * 256 + tid;
            int r = c >> 3, cc = (c & 7) * 8;
            cp_async16(&KVs(0)[r][cc], Kp + (size_t)r * HD + cc, true);  // rows < 197
        }
        CP_COMMIT();
        load_kv(1, 1, Kp);  // group B
    }

    // ---- S = Q K^T : 2 chunks of 128 kv cols ----
    for (int kc = 0; kc < 2; kc++) {
        CP_WAIT1();
        __syncthreads();
        wm::fragment<wm::accumulator, 16, 16, 16, float> sa[4][2];
#pragma unroll
        for (int i = 0; i < 4; i++)
#pragma unroll
            for (int j = 0; j < 2; j++) wm::fill_fragment(sa[i][j], 0.f);
#pragma unroll
        for (int ks = 0; ks < 4; ks++) {
            wm::fragment<wm::matrix_a, 16, 16, 16, __half, wm::row_major> qa[4];
#pragma unroll
            for (int i = 0; i < 4; i++)
                wm::load_matrix_sync(qa[i], &Qs[wmi * 64 + i * 16][ks * 16], 72);
#pragma unroll
            for (int j = 0; j < 2; j++) {
                wm::fragment<wm::matrix_b, 16, 16, 16, __half, wm::col_major> kb;
                wm::load_matrix_sync(kb, &KVs(kc)[wni * 32 + j * 16][ks * 16], 72);
#pragma unroll
                for (int i = 0; i < 4; i++) wm::mma_sync(sa[i][j], qa[i], kb, sa[i][j]);
            }
        }
#pragma unroll
        for (int i = 0; i < 4; i++)
#pragma unroll
            for (int j = 0; j < 2; j++)
                wm::store_matrix_sync(&S[wmi * 64 + i * 16][kc * 128 + wni * 32 + j * 16],
                                      sa[i][j], 256, wm::mem_row_major);
        __syncthreads();                       // K chunk consumed
        load_kv(kc, kc, Vp);                   // group C (V0) / group D (V1)
    }

    // ---- softmax (fp32), 16 rows per warp; overlaps V0 load ----
#pragma unroll
    for (int rr = 0; rr < 16; rr++) {
        int r = wid * 16 + rr;
        float mx = -1e30f;
        for (int j = lane; j < TKV; j += 32) mx = fmaxf(mx, S[r][j]);
#pragma unroll
        for (int o = 16; o; o >>= 1) mx = fmaxf(mx, __shfl_xor_sync(0xffffffffu, mx, o));
        float sum = 0.f;
        for (int j = lane; j < 256; j += 32) {
            float p = (j < TKV) ? __expf((S[r][j] - mx) * ATT_SCALE) : 0.f;
            S[r][j] = p;
            sum += p;
        }
#pragma unroll
        for (int o = 16; o; o >>= 1) sum += __shfl_xor_sync(0xffffffffu, sum, o);
        float inv = 1.f / sum;
        for (int j = lane; j < TKV; j += 32) S[r][j] *= inv;
    }
    __syncthreads();

    // ---- O = P V : 2 chunks of 128 ----
    wm::fragment<wm::accumulator, 16, 16, 16, float> oa[2][2];
#pragma unroll
    for (int i = 0; i < 2; i++)
#pragma unroll
        for (int j = 0; j < 2; j++) wm::fill_fragment(oa[i][j], 0.f);
    for (int kc = 0; kc < 2; kc++) {
        // convert P chunk (S already zeroed for cols >= TKV)
#pragma unroll
        for (int i = 0; i < 64; i++) {
            int e = i * 256 + tid;
            int r = e >> 7, cc = e & 127;
            P[r][cc] = __float2half_rn(S[r][kc * 128 + cc]);
        }
        if (kc == 0) { CP_WAIT1(); } else { CP_WAIT0(); }
        __syncthreads();                       // V(kc) + P ready
#pragma unroll
        for (int ks = 0; ks < 8; ks++) {
            wm::fragment<wm::matrix_a, 16, 16, 16, __half, wm::row_major> pa[2];
#pragma unroll
            for (int i = 0; i < 2; i++)
                wm::load_matrix_sync(pa[i], &P[pmi * 32 + i * 16][ks * 16], 136);
#pragma unroll
            for (int j = 0; j < 2; j++) {
                wm::fragment<wm::matrix_b, 16, 16, 16, __half, wm::row_major> vb;
                wm::load_matrix_sync(vb, &KVs(kc)[ks * 16][pni * 32 + j * 16], 72);
#pragma unroll
                for (int i = 0; i < 2; i++) wm::mma_sync(oa[i][j], pa[i], vb, oa[i][j]);
            }
        }
        __syncthreads();                       // P consumed before overwrite
    }
#pragma unroll
    for (int i = 0; i < 2; i++)
#pragma unroll
        for (int j = 0; j < 2; j++)
            wm::store_matrix_sync(&S[pmi * 32 + i * 16][pni * 32 + j * 16], oa[i][j], 256,
                                  wm::mem_row_major);
    __syncthreads();

    const int b = bh / NHEAD, hh = bh % NHEAD;
#pragma unroll
    for (int i = 0; i < 32; i++) {
        int e = i * 256 + tid;
        int r = e >> 6, cc = e & 63;
        int t = q0 + r;
        if (t < TQ)
            O_[((size_t)(b * TQ + t)) * CDIM + hh * HD + cc] = __float2half_rn(S[r][cc]);
    }
}

// ---------------- launch ----------------
extern "C" void kernel_launch(void* const* d_in, const int* in_sizes, int n_in,
                              void* d_out, int out_size)
{
    const float* x      = (const float*)d_in[0];
    const float* conv_w = (const float*)d_in[1];
    const float* gamma  = (const float*)d_in[2];
    const float* beta   = (const float*)d_in[3];
    const float* mean   = (const float*)d_in[4];
    const float* var    = (const float*)d_in[5];
    const float* w_q    = (const float*)d_in[6];
    const float* w_k    = (const float*)d_in[7];
    const float* w_v    = (const float*)d_in[8];
    const float* w_proj = (const float*)d_in[9];
    const float* b_proj = (const float*)d_in[10];
    float* out = (float*)d_out;

    __half *xq, *xk, *xv, *q, *k, *v, *at, *wh, *wl;
    cudaGetSymbolAddress((void**)&xq, g_xq);
    cudaGetSymbolAddress((void**)&xk, g_xk);
    cudaGetSymbolAddress((void**)&xv, g_xv);
    cudaGetSymbolAddress((void**)&q,  g_q);
    cudaGetSymbolAddress((void**)&k,  g_k);
    cudaGetSymbolAddress((void**)&v,  g_v);
    cudaGetSymbolAddress((void**)&at, g_at);
    cudaGetSymbolAddress((void**)&wh, g_wh);
    cudaGetSymbolAddress((void**)&wl, g_wl);

    const int WN = CDIM * CDIM;  // 147456
    split_w_all<<<(4 * WN) / 256, 256>>>(w_q, w_k, w_v, w_proj, wh, wl);

    conv_bn_kernel<28, 1><<<dim3(3, 25, BATCH), 128>>>(
        x, conv_w, gamma, beta, mean, var, xq);
    conv_bn_kernel<14, 2><<<dim3(3, 7, BATCH), 128>>>(
        x, conv_w + CDIM * 9, gamma + CDIM, beta + CDIM, mean + CDIM, var + CDIM, xk);
    conv_bn_kernel<14, 2><<<dim3(3, 7, BATCH), 128>>>(
        x, conv_w + 2 * CDIM * 9, gamma + 2 * CDIM, beta + 2 * CDIM, mean + 2 * CDIM,
        var + 2 * CDIM, xv);

    const int MQ = BATCH * TQ;    // 25120
    const int MKV = BATCH * TKV;  // 6304
    const int GEMM_SMEM = 69632;
    cudaFuncSetAttribute(gemm_half_kernel<true, false>,
                         cudaFuncAttributeMaxDynamicSharedMemorySize, GEMM_SMEM);
    cudaFuncSetAttribute(gemm_half_kernel<false, true>,
                         cudaFuncAttributeMaxDynamicSharedMemorySize, GEMM_SMEM);

    dim3 gq((MQ + 127) / 128, 3), gkv((MKV + 127) / 128, 3);
    gemm_half_kernel<true, false><<<gq, 256, GEMM_SMEM>>>(xq, wh, wl, nullptr,
                                                          nullptr, q, MQ, TQ);
    gemm_half_kernel<true, false><<<gkv, 256, GEMM_SMEM>>>(xk, wh + WN, wl + WN, nullptr,
                                                           nullptr, k, MKV, TKV);
    gemm_half_kernel<true, false><<<gkv, 256, GEMM_SMEM>>>(xv, wh + 2*WN, wl + 2*WN, nullptr,
                                                           nullptr, v, MKV, TKV);

    const int ATT_SMEM = 221184;
    cudaFuncSetAttribute(attn_kernel, cudaFuncAttributeMaxDynamicSharedMemorySize, ATT_SMEM);
    attn_kernel<<<dim3((TQ + 127) / 128, BATCH * NHEAD), 256, ATT_SMEM>>>(q, k, v, at);

    gemm_half_kernel<false, true><<<gq, 256, GEMM_SMEM>>>(at, wh + 3*WN, wl + 3*WN, b_proj,
                                                          out, nullptr, MQ, TQ);
}